// round 1
// baseline (speedup 1.0000x reference)
#include <cuda_runtime.h>

// Problem constants
#define N_ANCH_TOTAL 65536   // 16 * 64 * 64
#define BS           128
#define NNEG         2048
#define NPOS         64
#define THREADS      256

// Per-batch partial results: [b][0]=neg_mean, [b][1]=pos_mean, [b][2]=loc_mean
__device__ float g_batch_loss[BS * 3];

__device__ __forceinline__ float block_reduce_sum(float v, float* sbuf) {
    // warp reduce
    #pragma unroll
    for (int off = 16; off > 0; off >>= 1)
        v += __shfl_down_sync(0xFFFFFFFFu, v, off);
    int lane = threadIdx.x & 31;
    int wid  = threadIdx.x >> 5;
    if (lane == 0) sbuf[wid] = v;
    __syncthreads();
    // first warp reduces the 8 warp partials
    if (wid == 0) {
        v = (lane < (THREADS / 32)) ? sbuf[lane] : 0.0f;
        #pragma unroll
        for (int off = 4; off > 0; off >>= 1)
            v += __shfl_down_sync(0xFFFFFFFFu, v, off);
    }
    return v;  // valid in thread 0
}

__global__ __launch_bounds__(THREADS)
void per_batch_kernel(const float* __restrict__ cls,
                      const float* __restrict__ loc,
                      const float* __restrict__ gts,
                      const int*   __restrict__ pos_a,
                      const int*   __restrict__ neg_a,
                      const float* __restrict__ anchors) {
    const int b   = blockIdx.x;
    const int tid = threadIdx.x;

    const float* clsb = cls + (size_t)b * (2u * N_ANCH_TOTAL);
    const float* locb = loc + (size_t)b * (4u * N_ANCH_TOTAL);

    float neg_sum = 0.0f;
    // 2048 / 256 = 8 per thread, fully unrolled -> MLP 16 loads in flight
    #pragma unroll
    for (int i = 0; i < NNEG / THREADS; i++) {
        int a  = neg_a[b * NNEG + i * THREADS + tid];
        float l0 = __ldg(&clsb[a]);
        float l1 = __ldg(&clsb[N_ANCH_TOTAL + a]);
        float m  = fmaxf(l0, l1);
        float lse = m + logf(expf(l0 - m) + expf(l1 - m));
        neg_sum += lse - l0;   // -log p0
    }

    float pos_sum = 0.0f;
    float loc_sum = 0.0f;
    const float gx = gts[b * 4 + 0];
    const float gy = gts[b * 4 + 1];
    const float gw = gts[b * 4 + 2];
    const float gh = gts[b * 4 + 3];

    if (tid < NPOS) {
        int a  = pos_a[b * NPOS + tid];
        float l0 = __ldg(&clsb[a]);
        float l1 = __ldg(&clsb[N_ANCH_TOTAL + a]);
        float m  = fmaxf(l0, l1);
        float lse = m + logf(expf(l0 - m) + expf(l1 - m));
        pos_sum = lse - l1;    // -log p1

        float4 an = __ldg(&((const float4*)anchors)[a]);
        float t0 = (gx - an.x) / an.z;
        float t1 = (gy - an.y) / an.w;
        float t2 = logf(gw / an.z);
        float t3 = logf(gh / an.w);

        float p0 = __ldg(&locb[0 * N_ANCH_TOTAL + a]);
        float p1 = __ldg(&locb[1 * N_ANCH_TOTAL + a]);
        float p2 = __ldg(&locb[2 * N_ANCH_TOTAL + a]);
        float p3 = __ldg(&locb[3 * N_ANCH_TOTAL + a]);

        float d, ad;
        d = p0 - t0; ad = fabsf(d); loc_sum += (ad < 1.0f) ? 0.5f * d * d : ad - 0.5f;
        d = p1 - t1; ad = fabsf(d); loc_sum += (ad < 1.0f) ? 0.5f * d * d : ad - 0.5f;
        d = p2 - t2; ad = fabsf(d); loc_sum += (ad < 1.0f) ? 0.5f * d * d : ad - 0.5f;
        d = p3 - t3; ad = fabsf(d); loc_sum += (ad < 1.0f) ? 0.5f * d * d : ad - 0.5f;
    }

    __shared__ float sbuf[THREADS / 32];
    float r;

    r = block_reduce_sum(neg_sum, sbuf);
    if (tid == 0) g_batch_loss[b * 3 + 0] = r * (1.0f / NNEG);
    __syncthreads();

    r = block_reduce_sum(pos_sum, sbuf);
    if (tid == 0) g_batch_loss[b * 3 + 1] = r * (1.0f / NPOS);
    __syncthreads();

    r = block_reduce_sum(loc_sum, sbuf);
    if (tid == 0) g_batch_loss[b * 3 + 2] = r * (1.0f / (NPOS * 4));
}

__global__ __launch_bounds__(BS)
void final_reduce_kernel(float* __restrict__ out) {
    const int tid = threadIdx.x;   // 0..127, one per batch
    float n = g_batch_loss[tid * 3 + 0];
    float p = g_batch_loss[tid * 3 + 1];
    float l = g_batch_loss[tid * 3 + 2];

    __shared__ float sn[4], sp[4], sl[4];
    #pragma unroll
    for (int off = 16; off > 0; off >>= 1) {
        n += __shfl_down_sync(0xFFFFFFFFu, n, off);
        p += __shfl_down_sync(0xFFFFFFFFu, p, off);
        l += __shfl_down_sync(0xFFFFFFFFu, l, off);
    }
    int lane = tid & 31, wid = tid >> 5;
    if (lane == 0) { sn[wid] = n; sp[wid] = p; sl[wid] = l; }
    __syncthreads();
    if (tid == 0) {
        float neg_m = (sn[0] + sn[1] + sn[2] + sn[3]) * (1.0f / BS);
        float pos_m = (sp[0] + sp[1] + sp[2] + sp[3]) * (1.0f / BS);
        float loc_m = (sl[0] + sl[1] + sl[2] + sl[3]) * (1.0f / BS);
        float loss  = 0.5f * (0.5f * neg_m + 0.5f * pos_m) + 0.5f * loc_m;
        out[0] = loss;
        out[1] = neg_m;
        out[2] = pos_m;
        out[3] = loc_m;
    }
}

extern "C" void kernel_launch(void* const* d_in, const int* in_sizes, int n_in,
                              void* d_out, int out_size) {
    const float* cls     = (const float*)d_in[0];  // (128, 32, 64, 64)
    const float* loc     = (const float*)d_in[1];  // (128, 64, 64, 64)
    const float* gts     = (const float*)d_in[2];  // (128, 4)
    const int*   pos_a   = (const int*)  d_in[3];  // (128, 64)
    const int*   neg_a   = (const int*)  d_in[4];  // (128, 2048)
    const float* anchors = (const float*)d_in[5];  // (65536, 4)
    float* out = (float*)d_out;

    per_batch_kernel<<<BS, THREADS>>>(cls, loc, gts, pos_a, neg_a, anchors);
    final_reduce_kernel<<<1, BS>>>(out);
}